// round 13
// baseline (speedup 1.0000x reference)
#include <cuda_runtime.h>
#include <cuda_fp16.h>
#include <cstdint>
#include <math.h>

#define NH 8
#define HQ 1024
#define DD 128
#define NKV 8192
#define NCV 1024
#define TOT (NH*HQ*DD)

// ---------------- static scratch (no allocations allowed) ----------------
__device__ __align__(16) unsigned short g_qb[TOT];         // Q fp16 (pre-scaled)
__device__ __align__(16) unsigned short g_kb[NH*NKV*DD];   // K fp16
__device__ __align__(16) unsigned short g_vb[NH*NKV*DD];   // V fp16
__device__ __align__(16) unsigned short g_ckb[NH*NCV*DD];  // cK fp16
__device__ __align__(16) unsigned short g_cvb[NH*NCV*DD];  // cV fp16
__device__ __align__(16) __half g_zA[TOT];                 // teacher partial (quarters 0+1), unnormalized
__device__ __align__(16) __half g_zB[TOT];                 // teacher partial (quarters 2+3)
__device__ __align__(16) __half g_zc[TOT];                 // compressed z (normalized)
__device__ float g_lA[NH*HQ], g_lB[NH*HQ];
__device__ float g_part[256];
__device__ int g_cnt;

// ---------------- ptx helpers ----------------
__device__ __forceinline__ void ldsm4(uint32_t& r0, uint32_t& r1, uint32_t& r2, uint32_t& r3, uint32_t a) {
  asm volatile("ldmatrix.sync.aligned.m8n8.x4.shared.b16 {%0,%1,%2,%3}, [%4];"
               : "=r"(r0), "=r"(r1), "=r"(r2), "=r"(r3) : "r"(a));
}
__device__ __forceinline__ void ldsm4t(uint32_t& r0, uint32_t& r1, uint32_t& r2, uint32_t& r3, uint32_t a) {
  asm volatile("ldmatrix.sync.aligned.m8n8.x4.trans.shared.b16 {%0,%1,%2,%3}, [%4];"
               : "=r"(r0), "=r"(r1), "=r"(r2), "=r"(r3) : "r"(a));
}
__device__ __forceinline__ void mma16816(float* c, const uint32_t* a, uint32_t b0, uint32_t b1) {
  asm volatile("mma.sync.aligned.m16n8k16.row.col.f32.f16.f16.f32 "
               "{%0,%1,%2,%3}, {%4,%5,%6,%7}, {%8,%9}, {%0,%1,%2,%3};"
               : "+f"(c[0]), "+f"(c[1]), "+f"(c[2]), "+f"(c[3])
               : "r"(a[0]), "r"(a[1]), "r"(a[2]), "r"(a[3]), "r"(b0), "r"(b1));
}
__device__ __forceinline__ void mma16816h(uint32_t* c, const uint32_t* a, uint32_t b0, uint32_t b1) {
  asm volatile("mma.sync.aligned.m16n8k16.row.col.f16.f16.f16.f16 "
               "{%0,%1}, {%2,%3,%4,%5}, {%6,%7}, {%0,%1};"
               : "+r"(c[0]), "+r"(c[1])
               : "r"(a[0]), "r"(a[1]), "r"(a[2]), "r"(a[3]), "r"(b0), "r"(b1));
}
__device__ __forceinline__ void cpasync16(uint32_t saddr, const void* g) {
  asm volatile("cp.async.cg.shared.global [%0], [%1], 16;" :: "r"(saddr), "l"(g));
}
__device__ __forceinline__ void barg(int id) {
  asm volatile("bar.sync %0, 128;" :: "r"(id));
}

// ---------------- fused fp32 -> fp16 convert, 2x float4 per thread ----------------
#define Q4 262144
#define K4 2097152
#define CVT_TOT (3*Q4 + 2*K4)
#define CVT_PAIRS (CVT_TOT/2)

__global__ void cvt_all_kernel(const float4* __restrict__ q,
                               const float4* __restrict__ k,
                               const float4* __restrict__ v,
                               const float4* __restrict__ ck,
                               const float4* __restrict__ cv) {
  const float qscale = (float)(0.08838834764831845 * 1.4426950408889634);
  int p = blockIdx.x * 256 + threadIdx.x;
  int i = p * 2;
  const float4* src; uint4* dst; float sc = 1.f; int off;
  if (i < Q4)              { src = q;  dst = (uint4*)g_qb;  off = i;              sc = qscale; }
  else if (i < Q4 + K4)    { src = k;  dst = (uint4*)g_kb;  off = i - Q4; }
  else if (i < Q4 + 2*K4)  { src = v;  dst = (uint4*)g_vb;  off = i - Q4 - K4; }
  else if (i < 2*Q4 + 2*K4){ src = ck; dst = (uint4*)g_ckb; off = i - Q4 - 2*K4; }
  else                     { src = cv; dst = (uint4*)g_cvb; off = i - 2*Q4 - 2*K4; }
  float4 a = src[off], b = src[off + 1];
  __half2 h0 = __float22half2_rn(make_float2(a.x * sc, a.y * sc));
  __half2 h1 = __float22half2_rn(make_float2(a.z * sc, a.w * sc));
  __half2 h2 = __float22half2_rn(make_float2(b.x * sc, b.y * sc));
  __half2 h3 = __float22half2_rn(make_float2(b.z * sc, b.w * sc));
  uint4 o;
  o.x = *(uint32_t*)&h0; o.y = *(uint32_t*)&h1;
  o.z = *(uint32_t*)&h2; o.w = *(uint32_t*)&h3;
  dst[off >> 1] = o;
}

// ---------------- mma flash attention: M=32/warp, 128 q-rows/CTA, 2 KV groups ----------------
// smem: Q 32KB | groupA: K dbuf 32KB + V dbuf 32KB | groupB same
#define SM_Q 0
#define SM_GA 32768
#define SMEM_BYTES 163840

__global__ void __launch_bounds__(256, 1)
attn_mma_kernel() {
  extern __shared__ char smem[];
  const uint32_t smb = (uint32_t)__cvta_generic_to_shared(smem);
  const int tid = threadIdx.x;
  const int lane = tid & 31, warp = tid >> 5;
  const int group = warp >> 2, gwarp = warp & 3;
  const int gtid = tid & 127;
  const int g = lane >> 2, tig = lane & 3;
  const int within = lane & 7, sub = lane >> 3;
  const int rql = ((sub & 1) << 3) + within;
  const int csel = sub >> 1;
  const int barid = 1 + group;
  const int bid = blockIdx.x;

  int it0 = 0, nit = 1;
  if (bid >= 128) { int b = bid - 128; it0 = (b * 64) / 20; nit = ((b + 1) * 64) / 20 - it0; }

  const uint32_t kgbase = smb + SM_GA + group * 65536;   // K dbuf (2 x 16KB)
  const uint32_t vgbase = kgbase + 32768;                 // V dbuf (2 x 16KB)

  for (int ii = 0; ii < nit; ii++) {
    const unsigned short *Kb, *Vb; __half* Og; float* lpart = nullptr;
    int Tg, qrow0; bool teach;
    if (bid < 128) {
      teach = true;
      int h = bid >> 4, qt2 = (bid >> 1) & 7, qp = bid & 1;
      qrow0 = h * HQ + qt2 * 128;
      int quarter = qp * 2 + group;               // this group's KV quarter
      Kb = g_kb + ((size_t)h * NKV + (size_t)quarter * (NKV / 4)) * DD;
      Vb = g_vb + ((size_t)h * NKV + (size_t)quarter * (NKV / 4)) * DD;
      Tg = (NKV / 4) >> 6;                        // 32 tiles
      Og = qp ? g_zB : g_zA;
      lpart = qp ? g_lB : g_lA;
    } else {
      teach = false;
      int it = it0 + ii;
      int h = it >> 3, qt2 = it & 7;
      qrow0 = h * HQ + qt2 * 128;
      Kb = g_ckb + ((size_t)h * NCV + (size_t)group * (NCV / 2)) * DD;
      Vb = g_cvb + ((size_t)h * NCV + (size_t)group * (NCV / 2)) * DD;
      Tg = (NCV / 2) >> 6;                        // 8 tiles
      Og = g_zc;
    }

    // ---- prologue: Q (128 rows, all threads) + this group's K0/V0 ----
    {
      const unsigned short* qs = g_qb + (size_t)qrow0 * DD;
      for (int i = tid; i < 2048; i += 256) {
        int r = i >> 4, c = i & 15;
        uint32_t off = r * 256 + ((c ^ (r & 7)) << 4);
        cpasync16(smb + SM_Q + off, qs + r * DD + c * 8);
      }
      for (int i = gtid; i < 1024; i += 128) {
        int r = i >> 4, c = i & 15;
        uint32_t off = r * 256 + ((c ^ (r & 7)) << 4);
        cpasync16(kgbase + off, Kb + r * DD + c * 8);
        cpasync16(vgbase + off, Vb + r * DD + c * 8);
      }
      asm volatile("cp.async.commit_group;");
    }
    asm volatile("cp.async.wait_group 0;");
    __syncthreads();

    // ---- Q fragments: M=32 per warp (2 x 16-row halves), K=128 ----
    uint32_t qa[2][8][4];
#pragma unroll
    for (int mi = 0; mi < 2; mi++)
#pragma unroll
      for (int kt = 0; kt < 8; kt++) {
        int r = gwarp * 32 + mi * 16 + rql, c = 2 * kt + csel;
        ldsm4(qa[mi][kt][0], qa[mi][kt][1], qa[mi][kt][2], qa[mi][kt][3],
              smb + SM_Q + r * 256 + ((c ^ (r & 7)) << 4));
      }

    uint32_t o16[2][16][2];
#pragma unroll
    for (int mi = 0; mi < 2; mi++)
#pragma unroll
      for (int i = 0; i < 16; i++) { o16[mi][i][0] = 0u; o16[mi][i][1] = 0u; }
    float rs[2][2] = {{0.f, 0.f}, {0.f, 0.f}};

    for (int t = 0; t < Tg; t++) {
      const int buf = t & 1;
      asm volatile("cp.async.wait_group 0;");
      barg(barid);
      if (t + 1 < Tg) {
        const unsigned short* ks = Kb + (size_t)(t + 1) * 64 * DD;
        const unsigned short* vs = Vb + (size_t)(t + 1) * 64 * DD;
        const int bo = (buf ^ 1) * 16384;
        for (int i = gtid; i < 1024; i += 128) {
          int r = i >> 4, c = i & 15;
          uint32_t off = r * 256 + ((c ^ (r & 7)) << 4);
          cpasync16(kgbase + bo + off, ks + r * DD + c * 8);
          cpasync16(vgbase + bo + off, vs + r * DD + c * 8);
        }
        asm volatile("cp.async.commit_group;");
      }

      // ---- GEMM1 + softmax, np-outer (S lives only 16 regs at a time) ----
      uint32_t p[2][8][2];     // P fragments, both M halves
      const uint32_t kbase = kgbase + buf * 16384;
#pragma unroll
      for (int np = 0; np < 4; np++) {
        float s[2][2][4];
#pragma unroll
        for (int mi = 0; mi < 2; mi++)
#pragma unroll
          for (int j = 0; j < 2; j++) { s[mi][j][0] = s[mi][j][1] = s[mi][j][2] = s[mi][j][3] = 0.f; }
#pragma unroll
        for (int kt = 0; kt < 8; kt++) {
          int r = 16 * np + rql, c = 2 * kt + csel;
          uint32_t b0, b1, b2, b3;
          ldsm4(b0, b1, b2, b3, kbase + r * 256 + ((c ^ (r & 7)) << 4));
#pragma unroll
          for (int mi = 0; mi < 2; mi++) {
            mma16816(s[mi][0], qa[mi][kt], b0, b2);
            mma16816(s[mi][1], qa[mi][kt], b1, b3);
          }
        }
#pragma unroll
        for (int mi = 0; mi < 2; mi++) {
#pragma unroll
          for (int j = 0; j < 2; j++) {
            __half2 a = h2exp2(__float22half2_rn(make_float2(s[mi][j][0], s[mi][j][1])));
            __half2 b = h2exp2(__float22half2_rn(make_float2(s[mi][j][2], s[mi][j][3])));
            float2 fa = __half22float2(a), fb = __half22float2(b);
            rs[mi][0] += fa.x + fa.y;
            rs[mi][1] += fb.x + fb.y;
            p[mi][2 * np + j][0] = *(uint32_t*)&a;
            p[mi][2 * np + j][1] = *(uint32_t*)&b;
          }
        }
      }

      // ---- GEMM2: O += P V, f16 acc, V ldsm shared by both M halves ----
      const uint32_t vbase = vgbase + buf * 16384;
#pragma unroll
      for (int kt2 = 0; kt2 < 4; kt2++) {
#pragma unroll
        for (int dp = 0; dp < 8; dp++) {
          int r = 16 * kt2 + rql, c = 2 * dp + csel;
          uint32_t v0, v1, v2, v3;
          ldsm4t(v0, v1, v2, v3, vbase + r * 256 + ((c ^ (r & 7)) << 4));
#pragma unroll
          for (int mi = 0; mi < 2; mi++) {
            uint32_t pa[4] = {p[mi][2 * kt2][0], p[mi][2 * kt2][1],
                              p[mi][2 * kt2 + 1][0], p[mi][2 * kt2 + 1][1]};
            mma16816h(o16[mi][2 * dp], pa, v0, v1);
            mma16816h(o16[mi][2 * dp + 1], pa, v2, v3);
          }
        }
      }
    }

    // ---- final l reduction (quad) ----
#pragma unroll
    for (int mi = 0; mi < 2; mi++) {
      rs[mi][0] += __shfl_xor_sync(~0u, rs[mi][0], 1); rs[mi][0] += __shfl_xor_sync(~0u, rs[mi][0], 2);
      rs[mi][1] += __shfl_xor_sync(~0u, rs[mi][1], 1); rs[mi][1] += __shfl_xor_sync(~0u, rs[mi][1], 2);
    }

    // ---- merge the two groups (additive) via smem overlay ----
    __syncthreads();
    uint32_t* obuf = (uint32_t*)(smem + SM_GA);        // [128][68] u32, conflict-free
    float* lbuf = (float*)(smem + SM_GA + 34816);      // [128]

    if (group == 1) {
#pragma unroll
      for (int mi = 0; mi < 2; mi++) {
        const int r0 = gwarp * 32 + mi * 16 + g;
        if (tig == 0) { lbuf[r0] = rs[mi][0]; lbuf[r0 + 8] = rs[mi][1]; }
#pragma unroll
        for (int dt = 0; dt < 16; dt++) {
          obuf[r0 * 68 + 4 * dt + tig]       = o16[mi][dt][0];
          obuf[(r0 + 8) * 68 + 4 * dt + tig] = o16[mi][dt][1];
        }
      }
    }
    __syncthreads();

    if (group == 0) {
#pragma unroll
      for (int mi = 0; mi < 2; mi++) {
        const int r0 = gwarp * 32 + mi * 16 + g;
        const float l0 = rs[mi][0] + lbuf[r0];
        const float l1 = rs[mi][1] + lbuf[r0 + 8];
        if (teach) {
          if (tig == 0) { lpart[qrow0 + r0] = l0; lpart[qrow0 + r0 + 8] = l1; }
#pragma unroll
          for (int dt = 0; dt < 16; dt++) {
            int col = 8 * dt + 2 * tig;
            uint32_t pu0 = obuf[r0 * 68 + 4 * dt + tig];
            uint32_t pu1 = obuf[(r0 + 8) * 68 + 4 * dt + tig];
            __half2 a = __hadd2(*(__half2*)&o16[mi][dt][0], *(__half2*)&pu0);
            __half2 b = __hadd2(*(__half2*)&o16[mi][dt][1], *(__half2*)&pu1);
            *(__half2*)(Og + (size_t)(qrow0 + r0) * DD + col) = a;
            *(__half2*)(Og + (size_t)(qrow0 + r0 + 8) * DD + col) = b;
          }
        } else {
          const float inv0 = 1.f / l0, inv1 = 1.f / l1;
#pragma unroll
          for (int dt = 0; dt < 16; dt++) {
            int col = 8 * dt + 2 * tig;
            uint32_t pu0 = obuf[r0 * 68 + 4 * dt + tig];
            uint32_t pu1 = obuf[(r0 + 8) * 68 + 4 * dt + tig];
            float2 fa = __half22float2(__hadd2(*(__half2*)&o16[mi][dt][0], *(__half2*)&pu0));
            float2 fb = __half22float2(__hadd2(*(__half2*)&o16[mi][dt][1], *(__half2*)&pu1));
            __half2 wa = __float22half2_rn(make_float2(fa.x * inv0, fa.y * inv0));
            __half2 wb = __float22half2_rn(make_float2(fb.x * inv1, fb.y * inv1));
            *(__half2*)(Og + (size_t)(qrow0 + r0) * DD + col) = wa;
            *(__half2*)(Og + (size_t)(qrow0 + r0 + 8) * DD + col) = wb;
          }
        }
      }
    }
    __syncthreads();
  }
}

// ---------------- fused MSE with teacher partial merge (deterministic) ----------------
__global__ void mse_kernel(float* __restrict__ out) {
  __shared__ float red[256];
  __shared__ float rinv[32];
  __shared__ int lastflag;
  const int bid = blockIdx.x, tid = threadIdx.x;
  if (tid < 32) {
    int row = bid * 32 + tid;
    rinv[tid] = 1.f / (g_lA[row] + g_lB[row]);
  }
  __syncthreads();
  const __half2* zA = (const __half2*)g_zA + (size_t)bid * 2048;
  const __half2* zB = (const __half2*)g_zB + (size_t)bid * 2048;
  const __half2* zc = (const __half2*)g_zc + (size_t)bid * 2048;
  float s = 0.f;
  for (int i = tid; i < 2048; i += 256) {
    float ri = rinv[i >> 6];
    float2 a = __half22float2(zA[i]);
    float2 b = __half22float2(zB[i]);
    float2 c = __half22float2(zc[i]);
    float d0 = (a.x + b.x) * ri - c.x;
    float d1 = (a.y + b.y) * ri - c.y;
    s += d0 * d0 + d1 * d1;
  }
  red[tid] = s; __syncthreads();
  for (int o = 128; o > 0; o >>= 1) { if (tid < o) red[tid] += red[tid + o]; __syncthreads(); }
  if (tid == 0) {
    g_part[bid] = red[0];
    __threadfence();
    lastflag = (atomicAdd(&g_cnt, 1) == 255);
  }
  __syncthreads();
  if (lastflag) {
    __threadfence();
    red[tid] = g_part[tid];
    __syncthreads();
    for (int o = 128; o > 0; o >>= 1) { if (tid < o) red[tid] += red[tid + o]; __syncthreads(); }
    if (tid == 0) { out[0] = red[0] * (1.0f / (float)TOT); g_cnt = 0; }
  }
}

extern "C" void kernel_launch(void* const* d_in, const int* in_sizes, int n_in,
                              void* d_out, int out_size) {
  const float* q  = (const float*)d_in[0];
  const float* k  = (const float*)d_in[1];
  const float* v  = (const float*)d_in[2];
  const float* ck = (const float*)d_in[3];
  const float* cv = (const float*)d_in[4];
  (void)in_sizes; (void)n_in; (void)out_size;

  cudaFuncSetAttribute(attn_mma_kernel,
                       cudaFuncAttributeMaxDynamicSharedMemorySize, SMEM_BYTES);

  cvt_all_kernel<<<CVT_PAIRS / 256, 256>>>((const float4*)q, (const float4*)k,
                                           (const float4*)v, (const float4*)ck,
                                           (const float4*)cv);
  attn_mma_kernel<<<148, 256, SMEM_BYTES>>>();
  mse_kernel<<<256, 256>>>((float*)d_out);
}